// round 13
// baseline (speedup 1.0000x reference)
#include <cuda_runtime.h>
#include <cuda_fp16.h>
#include <cstdint>

#define FULLMASK 0xFFFFFFFFu

// ======================= device scratch (no allocs allowed) =======================
__device__ __align__(16) __half g_Mh[179u * 128u * 128u];   // per-block linear maps, fp16
__device__ __align__(16) __half g_Zh[2048u * 128u];         // z in fp16
__device__ __align__(16) float  g_XT[32u * 2048u];          // x transposed [i][s]
__device__ __align__(16) float  g_H1T[128u * 2048u];        // h1 fp32 [j][s]
__device__ __align__(16) float  g_H2T[128u * 2048u];        // h2 fp32 [j][s]
__device__ __align__(16) __half g_H2h[128u * 2048u];        // h2 fp16 [j][s] (for kC)
__device__ __align__(16) float  g_D0P[16u * 128u * 2048u];  // layer-0 delta partials
__device__ __align__(16) float  g_D1P[16u * 128u * 2048u];  // layer-1 delta partials
__device__ __align__(16) float  g_BD[3u * 128u * 2048u];    // bias deltas (blocks 32,161,178)

__device__ __forceinline__ uint32_t smem_u32(const void* p) {
    uint32_t a;
    asm("{ .reg .u64 t; cvta.to.shared.u64 t, %1; cvt.u32.u64 %0, t; }" : "=r"(a) : "l"(p));
    return a;
}
// PDL controls (sm_90+)
__device__ __forceinline__ void gdc_wait() {
#if __CUDA_ARCH__ >= 900
    asm volatile("griddepcontrol.wait;" ::: "memory");
#endif
}
__device__ __forceinline__ void gdc_launch() {
#if __CUDA_ARCH__ >= 900
    asm volatile("griddepcontrol.launch_dependents;");
#endif
}

// ======================= FWHT (contiguous layout) =======================
__device__ __forceinline__ void fwht128c(float &u0, float &u1, float &u2, float &u3, int lane) {
    float a0 = u0 + u1, a1 = u0 - u1;
    float a2 = u2 + u3, a3 = u2 - u3;
    u0 = a0 + a2; u2 = a0 - a2;
    u1 = a1 + a3; u3 = a1 - a3;
#pragma unroll
    for (int m = 1; m <= 16; m <<= 1) {
        float s = (lane & m) ? -1.0f : 1.0f;
        float p0 = __shfl_xor_sync(FULLMASK, u0, m);
        float p1 = __shfl_xor_sync(FULLMASK, u1, m);
        float p2 = __shfl_xor_sync(FULLMASK, u2, m);
        float p3 = __shfl_xor_sync(FULLMASK, u3, m);
        u0 = fmaf(s, u0, p0); u1 = fmaf(s, u1, p1);
        u2 = fmaf(s, u2, p2); u3 = fmaf(s, u3, p3);
    }
}

// ======================= K1: build M rows + z->fp16 + x transpose ================
__global__ __launch_bounds__(256)
void k1_build(const float* __restrict__ x, const float* __restrict__ z,
              const float* __restrict__ ffB, const float* __restrict__ ffG,
              const float* __restrict__ ffS, const int* __restrict__ ffP)
{
    __shared__ __align__(16) float sstg[8][128];
    const int tid = threadIdx.x, w = tid >> 5, lane = tid & 31;

    if (blockIdx.x >= 2928) {
        __shared__ float xs[256][33];
        int s0 = (blockIdx.x - 2928) * 256;
        const float4* xr = reinterpret_cast<const float4*>(x + (size_t)(s0 + tid) * 32);
#pragma unroll
        for (int i4 = 0; i4 < 8; i4++) {
            float4 v = xr[i4];
            xs[tid][i4 * 4 + 0] = v.x; xs[tid][i4 * 4 + 1] = v.y;
            xs[tid][i4 * 4 + 2] = v.z; xs[tid][i4 * 4 + 3] = v.w;
        }
        __syncthreads();
#pragma unroll
        for (int it = 0; it < 32; it++) {
            int idx = it * 256 + tid;
            int i = idx >> 8, sl = idx & 255;
            g_XT[(size_t)i * 2048 + s0 + sl] = xs[sl][i];
        }
        return;
    }
    if (blockIdx.x >= 2864) {
        int gt = (blockIdx.x - 2864) * 256 + tid;
        const float4* zf4 = reinterpret_cast<const float4*>(z);
        uint2* zb2 = reinterpret_cast<uint2*>(g_Zh);
#pragma unroll
        for (int it = 0; it < 4; it++) {
            int i = gt * 4 + it;
            float4 v = zf4[i];
            __half2 lo = __floats2half2_rn(v.x, v.y);
            __half2 hi = __floats2half2_rn(v.z, v.w);
            uint2 o;
            o.x = *reinterpret_cast<uint32_t*>(&lo);
            o.y = *reinterpret_cast<uint32_t*>(&hi);
            zb2[i] = o;
        }
        return;
    }

    const int rowid = blockIdx.x * 8 + w;       // 0..22911
    const int r = rowid >> 7, m = rowid & 127;
    const int o = r * 128;

    float4 g4 = reinterpret_cast<const float4*>(ffG + o)[lane];
    float4 b4 = reinterpret_cast<const float4*>(ffB + o)[lane];
    int4   p4 = reinterpret_cast<const int4*>(ffP + o)[lane];
    float  sm = ffS[o + m] * (1.0f / 128.0f);

    int e = lane << 2;
    float t0 = (__popc((e + 0) & m) & 1) ? -g4.x : g4.x;
    float t1 = (__popc((e + 1) & m) & 1) ? -g4.y : g4.y;
    float t2 = (__popc((e + 2) & m) & 1) ? -g4.z : g4.z;
    float t3 = (__popc((e + 3) & m) & 1) ? -g4.w : g4.w;

    float* stg = sstg[w];
    stg[p4.x] = t0; stg[p4.y] = t1; stg[p4.z] = t2; stg[p4.w] = t3;
    __syncwarp();
    float4 u = *reinterpret_cast<float4*>(stg + e);
    fwht128c(u.x, u.y, u.z, u.w, lane);

    __half2 lo = __floats2half2_rn(sm * b4.x * u.x, sm * b4.y * u.y);
    __half2 hi = __floats2half2_rn(sm * b4.z * u.z, sm * b4.w * u.w);
    uint2 ov;
    ov.x = *reinterpret_cast<uint32_t*>(&lo);
    ov.y = *reinterpret_cast<uint32_t*>(&hi);
    reinterpret_cast<uint2*>(g_Mh + (size_t)rowid * 128)[lane] = ov;
}

// ======================= shared MMA machinery =====================================
#define SWZ(row, ch) ((uint32_t)((row) * 256 + (((ch) ^ ((row) & 7)) << 4)))

__device__ __forceinline__ void ldmx4(uint32_t &r0, uint32_t &r1, uint32_t &r2, uint32_t &r3, uint32_t a) {
    asm volatile("ldmatrix.sync.aligned.m8n8.x4.shared.b16 {%0,%1,%2,%3}, [%4];"
                 : "=r"(r0), "=r"(r1), "=r"(r2), "=r"(r3) : "r"(a));
}
__device__ __forceinline__ void ldmx2(uint32_t &r0, uint32_t &r1, uint32_t a) {
    asm volatile("ldmatrix.sync.aligned.m8n8.x2.shared.b16 {%0,%1}, [%2];"
                 : "=r"(r0), "=r"(r1) : "r"(a));
}
__device__ __forceinline__ void mma_f16(float c[4], const uint32_t a[4], const uint32_t b[2]) {
    asm volatile(
        "mma.sync.aligned.m16n8k16.row.col.f32.f16.f16.f32 "
        "{%0,%1,%2,%3}, {%4,%5,%6,%7}, {%8,%9}, {%0,%1,%2,%3};"
        : "+f"(c[0]), "+f"(c[1]), "+f"(c[2]), "+f"(c[3])
        : "r"(a[0]), "r"(a[1]), "r"(a[2]), "r"(a[3]), "r"(b[0]), "r"(b[1]));
}

__device__ __forceinline__ void fill_tile(char* sm, const uint4* __restrict__ src, int tid) {
#pragma unroll
    for (int it = 0; it < 8; it++) {
        int c = it * 256 + tid;
        int row = c >> 4, ch = c & 15;
        *reinterpret_cast<uint4*>(sm + SWZ(row, ch)) = src[c];
    }
}

// 128x128 CTA tile, 8 warps (2x4), warp tile 64x32 (bias + kC path)
__device__ __forceinline__ void mma_tile(const char* smA, const char* smB,
                                         int lane, int wm, int wn, float acc[4][4][4]) {
#pragma unroll
    for (int mt = 0; mt < 4; mt++)
#pragma unroll
        for (int nt = 0; nt < 4; nt++)
#pragma unroll
            for (int q = 0; q < 4; q++) acc[mt][nt][q] = 0.0f;
    uint32_t sbA = smem_u32(smA), sbB = smem_u32(smB);
    const int mbase = wm * 64, nbase = wn * 32;
    const int arow = lane & 15, ach = lane >> 4;
    const int brow = lane & 7,  bch = (lane >> 3) & 1;
#pragma unroll
    for (int ks = 0; ks < 8; ks++) {
        const int k0c = ks * 2;
        uint32_t a[4][4], b[4][2];
#pragma unroll
        for (int mt = 0; mt < 4; mt++)
            ldmx4(a[mt][0], a[mt][1], a[mt][2], a[mt][3],
                  sbA + SWZ(mbase + mt * 16 + arow, k0c + ach));
#pragma unroll
        for (int nt = 0; nt < 4; nt++)
            ldmx2(b[nt][0], b[nt][1], sbB + SWZ(nbase + nt * 8 + brow, k0c + bch));
#pragma unroll
        for (int mt = 0; mt < 4; mt++)
#pragma unroll
            for (int nt = 0; nt < 4; nt++)
                mma_f16(acc[mt][nt], a[mt], b[nt]);
    }
}

template <int N>
__device__ __forceinline__ void red3(float* p) {
#pragma unroll
    for (int m = 4; m <= 16; m <<= 1)
#pragma unroll
        for (int i = 0; i < N; i++) p[i] += __shfl_xor_sync(FULLMASK, p[i], m);
}

// ======================= kD: unified delta GEMM (PDL-aware) =======================
// Warp tile 64M x 32N (2 wm x 4 wn). Per-ks all 6 LDSMs issued back-to-back
// (2 z + 4 A) so LDSM latency is pipelined, then hmul b-build, then 16 MMAs.
// mode 0: D0[j,s] over K=(i,k) 4096; 16 K-splits x 2 chunks; + 3 bias-block CTAs.
// mode 1: D1[j,s] over K=(e,k) 16384; 16 K-splits x 8 chunks.
__global__ __launch_bounds__(256, 2)
void kD(int mode)
{
    extern __shared__ char sm[];
    const int tid = threadIdx.x, w = tid >> 5, lane = tid & 31;
    const int s0 = blockIdx.y * 128;

    const __half* Abase; int arow; const float* H; float* dstP; int nch, nb;
    if (mode == 0) { Abase = g_Mh;                arow = 4096;  H = g_XT;  dstP = g_D0P; nch = 2; nb = 16; }
    else           { Abase = g_Mh + 33u * 16384u; arow = 16384; H = g_H1T; dstP = g_D1P; nch = 8; nb = 1 << 30; }

    if (mode == 0) { gdc_wait(); gdc_launch(); }

    if ((int)blockIdx.x >= nb) {
        // plain bias-block GEMM tile -> g_BD
        int bi = blockIdx.x - nb;
        int r = (bi == 0) ? 32 : (bi == 1) ? 161 : 178;
        char* smA = sm; char* smB = sm + 32768;
        fill_tile(smA, reinterpret_cast<const uint4*>(g_Mh + (size_t)r * 16384), tid);
        fill_tile(smB, reinterpret_cast<const uint4*>(g_Zh + (size_t)s0 * 128), tid);
        __syncthreads();
        float acc[4][4][4];
        mma_tile(smA, smB, lane, w & 1, w >> 1, acc);
        float* dst = g_BD + (size_t)bi * 128 * 2048;
        const int wm2 = w & 1, wn2 = w >> 1;
#pragma unroll
        for (int mt = 0; mt < 4; mt++)
#pragma unroll
            for (int qh = 0; qh < 2; qh++) {
                const int e = wm2 * 64 + mt * 16 + (lane >> 2) + 8 * qh;
#pragma unroll
                for (int nt = 0; nt < 4; nt++) {
                    const int s = wn2 * 32 + nt * 8 + 2 * (lane & 3);
                    *reinterpret_cast<float2*>(dst + (size_t)e * 2048 + s0 + s) =
                        make_float2(acc[mt][nt][2 * qh + 0], acc[mt][nt][2 * qh + 1]);
                }
            }
        return;
    }

    char*  zsm  = sm;                                      // 32K z tile (swizzled)
    float* hsm  = reinterpret_cast<float*>(sm + 32768);    // [nch e][128 s]
    char*  abuf = sm + 36864;                              // 2 x 32K A stages
    const int ksp = blockIdx.x;
    const int e0 = ksp * nch;
    const int wm = w & 1, wn = w >> 1;                     // 2 x 4 warp grid
    const int mbase = wm * 64, nbase = wn * 32;

    auto issueA = [&](int c) {
        char* buf = abuf + (c & 1) * 32768;
        const char* base = reinterpret_cast<const char*>(Abase) + (size_t)(e0 + c) * 256;
#pragma unroll
        for (int it = 0; it < 8; it++) {
            int idx = it * 256 + tid;
            int row = idx >> 4, ch = idx & 15;
            const char* src = base + (size_t)row * arow * 2 + ch * 16;
            uint32_t dst = smem_u32(buf + SWZ(row, ch));
            asm volatile("cp.async.cg.shared.global [%0], [%1], 16;" :: "r"(dst), "l"(src));
        }
        asm volatile("cp.async.commit_group;");
    };

    // Prologue (mode 1: reads only k1 outputs — ≥2 launches back — legal pre-wait)
    issueA(0);
    if (nch > 1) issueA(1);
#pragma unroll
    for (int it = 0; it < 8; it++) {
        int c = it * 256 + tid;
        int row = c >> 4, ch = c & 15;
        *reinterpret_cast<uint4*>(zsm + SWZ(row, ch)) =
            reinterpret_cast<const uint4*>(g_Zh + (size_t)s0 * 128)[c];
    }

    if (mode == 1) { gdc_wait(); gdc_launch(); }

    for (int c = tid; c < nch * 128; c += 256) {
        int ce = c >> 7, s = c & 127;
        hsm[ce * 128 + s] = H[(size_t)(e0 + ce) * 2048 + s0 + s];
    }

    float acc[4][4][4];
#pragma unroll
    for (int mt = 0; mt < 4; mt++)
#pragma unroll
        for (int nt = 0; nt < 4; nt++)
#pragma unroll
            for (int q = 0; q < 4; q++) acc[mt][nt][q] = 0.0f;

    const int arl = lane & 15, ach = lane >> 4;
    const int nidx = lane >> 2;
    const int bro = ((lane >> 4) << 3) + (lane & 7);   // 16-row x4 B load pattern
    const int bch = (lane >> 3) & 1;
    const uint32_t sbB = smem_u32(zsm);

#pragma unroll 1
    for (int c = 0; c < nch; c++) {
        if (c < nch - 1) asm volatile("cp.async.wait_group 1;");
        else             asm volatile("cp.async.wait_group 0;");
        __syncthreads();
        uint32_t sbA = smem_u32(abuf + (c & 1) * 32768);
        __half2 hs[4];
#pragma unroll
        for (int nt = 0; nt < 4; nt++)
            hs[nt] = __float2half2_rn(hsm[c * 128 + nbase + nt * 8 + nidx]);
#pragma unroll
        for (int ks = 0; ks < 8; ks++) {
            // issue ALL fragment loads back-to-back: 2 z-ldmx4 + 4 a-ldmx4
            uint32_t z4[2][4];
#pragma unroll
            for (int p = 0; p < 2; p++)
                ldmx4(z4[p][0], z4[p][1], z4[p][2], z4[p][3],
                      sbB + SWZ(nbase + p * 16 + bro, ks * 2 + bch));
            uint32_t a4[4][4];
#pragma unroll
            for (int mt = 0; mt < 4; mt++)
                ldmx4(a4[mt][0], a4[mt][1], a4[mt][2], a4[mt][3],
                      sbA + SWZ(mbase + mt * 16 + arl, ks * 2 + ach));
            // build B fragments (z latency overlapped by a-loads in flight)
            uint32_t b[4][2];
#pragma unroll
            for (int p = 0; p < 2; p++)
#pragma unroll
                for (int half = 0; half < 2; half++) {
                    const int nt = 2 * p + half;
                    __half2 b0h = __hmul2(*reinterpret_cast<__half2*>(&z4[p][2 * half + 0]), hs[nt]);
                    __half2 b1h = __hmul2(*reinterpret_cast<__half2*>(&z4[p][2 * half + 1]), hs[nt]);
                    b[nt][0] = *reinterpret_cast<uint32_t*>(&b0h);
                    b[nt][1] = *reinterpret_cast<uint32_t*>(&b1h);
                }
            // 16 MMAs
#pragma unroll
            for (int mt = 0; mt < 4; mt++)
#pragma unroll
                for (int nt = 0; nt < 4; nt++)
                    mma_f16(acc[mt][nt], a4[mt], b[nt]);
        }
        __syncthreads();
        if (c + 2 < nch) issueA(c + 2);
    }

    float* dst = dstP + (size_t)ksp * 128 * 2048;
#pragma unroll
    for (int mt = 0; mt < 4; mt++)
#pragma unroll
        for (int qh = 0; qh < 2; qh++) {
            const int j = mbase + mt * 16 + (lane >> 2) + 8 * qh;
#pragma unroll
            for (int nt = 0; nt < 4; nt++) {
                const int s = nbase + nt * 8 + 2 * (lane & 3);
                *reinterpret_cast<float2*>(dst + (size_t)j * 2048 + s0 + s) =
                    make_float2(acc[mt][nt][2 * qh + 0], acc[mt][nt][2 * qh + 1]);
            }
        }
}

// ======================= h1fin: h1 = relu(W0 x + b0 + bd0 + sum(D0P)) =============
__global__ __launch_bounds__(256)
void h1fin(const float* __restrict__ x, const float* __restrict__ W0, const float* __restrict__ b0)
{
    __shared__ float xsm[128 * 32];
    __shared__ float w0sm[16 * 32];
    const int tid = threadIdx.x;
    const int s0 = blockIdx.x * 128, jg = blockIdx.y;

    for (int c = tid; c < 4096; c += 256) {
        int s = c >> 5, i = c & 31;
        xsm[s * 32 + i] = x[(s0 + s) * 32 + i];
    }
    for (int c = tid; c < 512; c += 256) w0sm[c] = W0[jg * 512 + c];
    __syncthreads();

    gdc_wait(); gdc_launch();

    const int s = tid & 127, jh = tid >> 7;
#pragma unroll
    for (int jj = 0; jj < 8; jj++) {
        const int jl = jh * 8 + jj, j = jg * 16 + jl;
        float a = b0[j] + g_BD[(size_t)j * 2048 + s0 + s];
#pragma unroll
        for (int p = 0; p < 16; p++)
            a += g_D0P[((size_t)p * 128 + j) * 2048 + s0 + s];
#pragma unroll
        for (int i = 0; i < 32; i++) a = fmaf(w0sm[jl * 32 + i], xsm[s * 32 + i], a);
        g_H1T[(size_t)j * 2048 + s0 + s] = fmaxf(a, 0.0f);
    }
}

// ======================= h2fin: h2 = relu(W1 h1 + b1 + bd1 + sum(D1P)) ============
__global__ __launch_bounds__(256)
void h2fin(const float* __restrict__ W1, const float* __restrict__ b1)
{
    extern __shared__ float smf[];
    float* h1sm = smf;            // [128 e][128 s]
    float* w1sm = smf + 16384;    // [16][128]
    const int tid = threadIdx.x;
    const int s0 = blockIdx.x * 128, jg = blockIdx.y;

    for (int c = tid; c < 4096; c += 256) {
        int e = c >> 5, ch = c & 31;
        reinterpret_cast<float4*>(h1sm)[c] =
            *reinterpret_cast<const float4*>(g_H1T + (size_t)e * 2048 + s0 + ch * 4);
    }
    for (int c = tid; c < 2048; c += 256) w1sm[c] = W1[jg * 2048 + c];
    __syncthreads();

    gdc_wait(); gdc_launch();

    const int s = tid & 127, jh = tid >> 7;
    float a[8];
#pragma unroll
    for (int jj = 0; jj < 8; jj++) {
        const int j = jg * 16 + jh * 8 + jj;
        float acc = b1[j] + g_BD[(size_t)(128 + j) * 2048 + s0 + s];
#pragma unroll
        for (int p = 0; p < 16; p++)
            acc += g_D1P[((size_t)p * 128 + j) * 2048 + s0 + s];
        a[jj] = acc;
    }
#pragma unroll 4
    for (int e = 0; e < 128; e++) {
        const float h = h1sm[e * 128 + s];
#pragma unroll
        for (int jj = 0; jj < 8; jj++)
            a[jj] = fmaf(w1sm[(jh * 8 + jj) * 128 + e], h, a[jj]);
    }
#pragma unroll
    for (int jj = 0; jj < 8; jj++) {
        const int j = jg * 16 + jh * 8 + jj;
        float v = fmaxf(a[jj], 0.0f);
        g_H2T[(size_t)j * 2048 + s0 + s] = v;
        g_H2h[(size_t)j * 2048 + s0 + s] = __float2half(v);
    }
}

// ======================= KC: layer-2 blocks (162..177) + output ===================
// h2 tile fp16 (32K) -> smem ~97K -> 2 CTAs/SM, single co-resident wave.
__global__ __launch_bounds__(256, 2)
void kC(const float* __restrict__ W2, const float* __restrict__ b2, float* __restrict__ out)
{
    extern __shared__ char sm[];
    char* smA = sm;
    char* smB = sm + 32768;
    __half* h2sm = reinterpret_cast<__half*>(sm + 65536);         // [128 e][128 s] fp16 (32K)
    float* w2sm = reinterpret_cast<float*>(sm + 65536 + 32768);   // [128]
    float* sd = w2sm + 128;                                       // [2][128]
    const int tid = threadIdx.x, w = tid >> 5, lane = tid & 31;
    const int wm = w & 1, wn = w >> 1;
    const int jj = blockIdx.x;
    const int s0 = blockIdx.y * 128;

    // prologue: A/z tiles (k1 data) + W2 — overlaps h2fin
    fill_tile(smA, reinterpret_cast<const uint4*>(g_Mh + (size_t)(162 + jj) * 16384), tid);
    fill_tile(smB, reinterpret_cast<const uint4*>(g_Zh + (size_t)s0 * 128), tid);
    if (tid < 128) w2sm[tid] = W2[jj * 128 + tid];

    gdc_wait(); gdc_launch();

    // h2 fp16 tile: 128 rows x 256B = 2048 uint4 chunks
    for (int c = tid; c < 2048; c += 256) {
        int e = c >> 4, ch = c & 15;
        reinterpret_cast<uint4*>(h2sm)[e * 16 + ch] =
            *reinterpret_cast<const uint4*>(g_H2h + (size_t)e * 2048 + s0 + ch * 8);
    }
    __syncthreads();

    float acc[4][4][4];
    mma_tile(smA, smB, lane, wm, wn, acc);

    float pb[8];
#pragma unroll
    for (int i = 0; i < 8; i++) pb[i] = 0.0f;
#pragma unroll
    for (int mt = 0; mt < 4; mt++)
#pragma unroll
        for (int qh = 0; qh < 2; qh++) {
            const int e = wm * 64 + mt * 16 + (lane >> 2) + 8 * qh;
            const float wv = w2sm[e];
            const __half2* hrow = reinterpret_cast<const __half2*>(h2sm + e * 128);
#pragma unroll
            for (int nt = 0; nt < 4; nt++) {
                const int sb = wn * 32 + nt * 8 + 2 * (lane & 3);
                float2 hv = __half22float2(hrow[sb >> 1]);
                pb[nt * 2 + 0] += (acc[mt][nt][2 * qh + 0] + wv) * hv.x;
                pb[nt * 2 + 1] += (acc[mt][nt][2 * qh + 1] + wv) * hv.y;
            }
        }
    red3<8>(pb);
    if (lane < 4) {
#pragma unroll
        for (int nt = 0; nt < 4; nt++)
#pragma unroll
            for (int q01 = 0; q01 < 2; q01++)
                sd[wm * 128 + wn * 32 + nt * 8 + 2 * lane + q01] = pb[nt * 2 + q01];
    }
    __syncthreads();
    if (tid < 128)
        out[(size_t)(s0 + tid) * 16 + jj] =
            b2[jj] + g_BD[(size_t)(256 + jj) * 2048 + s0 + tid] + sd[tid] + sd[128 + tid];
}

// ======================= launch ===================================================
template <typename F, typename... Args>
static inline void launch_pdl(F kern, dim3 grid, dim3 block, size_t smem, Args... args) {
    cudaLaunchConfig_t cfg = {};
    cfg.gridDim = grid;
    cfg.blockDim = block;
    cfg.dynamicSmemBytes = smem;
    cfg.stream = 0;
    cudaLaunchAttribute attrs[1];
    attrs[0].id = cudaLaunchAttributeProgrammaticStreamSerialization;
    attrs[0].val.programmaticStreamSerializationAllowed = 1;
    cfg.attrs = attrs;
    cfg.numAttrs = 1;
    cudaLaunchKernelEx(&cfg, kern, args...);
}

extern "C" void kernel_launch(void* const* d_in, const int* in_sizes, int n_in,
                              void* d_out, int out_size) {
    (void)in_sizes; (void)n_in; (void)out_size;
    const float* x   = (const float*)d_in[0];
    const float* z   = (const float*)d_in[1];
    const float* W0  = (const float*)d_in[2];
    const float* b0  = (const float*)d_in[3];
    const float* W1  = (const float*)d_in[4];
    const float* b1  = (const float*)d_in[5];
    const float* W2  = (const float*)d_in[6];
    const float* b2  = (const float*)d_in[7];
    const float* ffB = (const float*)d_in[8];
    const float* ffG = (const float*)d_in[9];
    const float* ffS = (const float*)d_in[10];
    const int*   ffP = (const int*)d_in[11];
    float* out = (float*)d_out;

    cudaFuncSetAttribute(kD, cudaFuncAttributeMaxDynamicSharedMemorySize, 102400);
    cudaFuncSetAttribute(h2fin, cudaFuncAttributeMaxDynamicSharedMemorySize, 73728);
    cudaFuncSetAttribute(kC, cudaFuncAttributeMaxDynamicSharedMemorySize, 100352);

    k1_build<<<2936, 256>>>(x, z, ffB, ffG, ffS, ffP);
    launch_pdl(kD, dim3(19, 16), dim3(256), (size_t)102400, 0);     // D0 partials + bias blocks
    launch_pdl(h1fin, dim3(16, 8), dim3(256), (size_t)0, x, W0, b0);
    launch_pdl(kD, dim3(16, 16), dim3(256), (size_t)102400, 1);     // D1 partials
    launch_pdl(h2fin, dim3(16, 8), dim3(256), (size_t)73728, W1, b1);
    launch_pdl(kC, dim3(16, 16), dim3(256), (size_t)100352, W2, b2, out);
}

// round 14
// speedup vs baseline: 1.0161x; 1.0161x over previous
#include <cuda_runtime.h>
#include <cuda_fp16.h>
#include <cstdint>

#define FULLMASK 0xFFFFFFFFu

// ======================= device scratch (no allocs allowed) =======================
__device__ __align__(16) __half g_Mh[179u * 128u * 128u];   // per-block linear maps, fp16
__device__ __align__(16) __half g_Zh[2048u * 128u];         // z in fp16
__device__ __align__(16) float  g_XT[32u * 2048u];          // x transposed [i][s]
__device__ __align__(16) float  g_H1T[128u * 2048u];        // h1 fp32 [j][s]
__device__ __align__(16) float  g_H2T[128u * 2048u];        // h2 fp32 [j][s]
__device__ __align__(16) __half g_H2h[128u * 2048u];        // h2 fp16 [j][s] (for kC)
__device__ __align__(16) float  g_D0P[16u * 128u * 2048u];  // layer-0 delta partials
__device__ __align__(16) float  g_D1P[16u * 128u * 2048u];  // layer-1 delta partials
__device__ __align__(16) float  g_BD[3u * 128u * 2048u];    // bias deltas (blocks 32,161,178)

__device__ __forceinline__ uint32_t smem_u32(const void* p) {
    uint32_t a;
    asm("{ .reg .u64 t; cvta.to.shared.u64 t, %1; cvt.u32.u64 %0, t; }" : "=r"(a) : "l"(p));
    return a;
}
// PDL controls (sm_90+)
__device__ __forceinline__ void gdc_wait() {
#if __CUDA_ARCH__ >= 900
    asm volatile("griddepcontrol.wait;" ::: "memory");
#endif
}
__device__ __forceinline__ void gdc_launch() {
#if __CUDA_ARCH__ >= 900
    asm volatile("griddepcontrol.launch_dependents;");
#endif
}

// ======================= FWHT (contiguous layout) =======================
__device__ __forceinline__ void fwht128c(float &u0, float &u1, float &u2, float &u3, int lane) {
    float a0 = u0 + u1, a1 = u0 - u1;
    float a2 = u2 + u3, a3 = u2 - u3;
    u0 = a0 + a2; u2 = a0 - a2;
    u1 = a1 + a3; u3 = a1 - a3;
#pragma unroll
    for (int m = 1; m <= 16; m <<= 1) {
        float s = (lane & m) ? -1.0f : 1.0f;
        float p0 = __shfl_xor_sync(FULLMASK, u0, m);
        float p1 = __shfl_xor_sync(FULLMASK, u1, m);
        float p2 = __shfl_xor_sync(FULLMASK, u2, m);
        float p3 = __shfl_xor_sync(FULLMASK, u3, m);
        u0 = fmaf(s, u0, p0); u1 = fmaf(s, u1, p1);
        u2 = fmaf(s, u2, p2); u3 = fmaf(s, u3, p3);
    }
}

// ======================= K1: build M rows + z->fp16 + x transpose ================
// One warp builds 8 rows of ONE block r, loading ffB/ffG/ffP once (L2 traffic /8).
// Grid: 358 M-CTAs (2864 warps) + 64 zconv CTAs + 8 xT CTAs = 430.
__global__ __launch_bounds__(256)
void k1_build(const float* __restrict__ x, const float* __restrict__ z,
              const float* __restrict__ ffB, const float* __restrict__ ffG,
              const float* __restrict__ ffS, const int* __restrict__ ffP)
{
    __shared__ __align__(16) float sstg[8][2][128];
    const int tid = threadIdx.x, w = tid >> 5, lane = tid & 31;

    if (blockIdx.x >= 422) {
        // x transpose: 8 blocks x 256 samples
        __shared__ float xs[256][33];
        int s0 = (blockIdx.x - 422) * 256;
        const float4* xr = reinterpret_cast<const float4*>(x + (size_t)(s0 + tid) * 32);
#pragma unroll
        for (int i4 = 0; i4 < 8; i4++) {
            float4 v = xr[i4];
            xs[tid][i4 * 4 + 0] = v.x; xs[tid][i4 * 4 + 1] = v.y;
            xs[tid][i4 * 4 + 2] = v.z; xs[tid][i4 * 4 + 3] = v.w;
        }
        __syncthreads();
#pragma unroll
        for (int it = 0; it < 32; it++) {
            int idx = it * 256 + tid;
            int i = idx >> 8, sl = idx & 255;
            g_XT[(size_t)i * 2048 + s0 + sl] = xs[sl][i];
        }
        return;
    }
    if (blockIdx.x >= 358) {
        // z (fp32) -> fp16
        int gt = (blockIdx.x - 358) * 256 + tid;
        const float4* zf4 = reinterpret_cast<const float4*>(z);
        uint2* zb2 = reinterpret_cast<uint2*>(g_Zh);
#pragma unroll
        for (int it = 0; it < 4; it++) {
            int i = gt * 4 + it;
            float4 v = zf4[i];
            __half2 lo = __floats2half2_rn(v.x, v.y);
            __half2 hi = __floats2half2_rn(v.z, v.w);
            uint2 o;
            o.x = *reinterpret_cast<uint32_t*>(&lo);
            o.y = *reinterpret_cast<uint32_t*>(&hi);
            zb2[i] = o;
        }
        return;
    }

    const int wg = blockIdx.x * 8 + w;        // 0..2863 (warp-group id)
    const int r  = wg >> 4;                   // block 0..178
    const int mb = (wg & 15) * 8;             // first row of this warp's 8
    const int o  = r * 128;

    float4 g4 = reinterpret_cast<const float4*>(ffG + o)[lane];
    float4 b4 = reinterpret_cast<const float4*>(ffB + o)[lane];
    int4   p4 = reinterpret_cast<const int4*>(ffP + o)[lane];

    const int e = lane << 2;
#pragma unroll 1
    for (int q = 0; q < 8; q++) {
        const int m = mb + q;
        const float smv = ffS[o + m] * (1.0f / 128.0f);   // uniform, cached

        float t0 = (__popc((e + 0) & m) & 1) ? -g4.x : g4.x;
        float t1 = (__popc((e + 1) & m) & 1) ? -g4.y : g4.y;
        float t2 = (__popc((e + 2) & m) & 1) ? -g4.z : g4.z;
        float t3 = (__popc((e + 3) & m) & 1) ? -g4.w : g4.w;

        float* stg = sstg[w][q & 1];
        stg[p4.x] = t0; stg[p4.y] = t1; stg[p4.z] = t2; stg[p4.w] = t3;
        __syncwarp();
        float4 u = *reinterpret_cast<float4*>(stg + e);
        fwht128c(u.x, u.y, u.z, u.w, lane);

        __half2 lo = __floats2half2_rn(smv * b4.x * u.x, smv * b4.y * u.y);
        __half2 hi = __floats2half2_rn(smv * b4.z * u.z, smv * b4.w * u.w);
        uint2 ov;
        ov.x = *reinterpret_cast<uint32_t*>(&lo);
        ov.y = *reinterpret_cast<uint32_t*>(&hi);
        reinterpret_cast<uint2*>(g_Mh + ((size_t)r * 128 + m) * 128)[lane] = ov;
    }
}

// ======================= shared MMA machinery =====================================
#define SWZ(row, ch) ((uint32_t)((row) * 256 + (((ch) ^ ((row) & 7)) << 4)))

__device__ __forceinline__ void ldmx4(uint32_t &r0, uint32_t &r1, uint32_t &r2, uint32_t &r3, uint32_t a) {
    asm volatile("ldmatrix.sync.aligned.m8n8.x4.shared.b16 {%0,%1,%2,%3}, [%4];"
                 : "=r"(r0), "=r"(r1), "=r"(r2), "=r"(r3) : "r"(a));
}
__device__ __forceinline__ void ldmx2(uint32_t &r0, uint32_t &r1, uint32_t a) {
    asm volatile("ldmatrix.sync.aligned.m8n8.x2.shared.b16 {%0,%1}, [%2];"
                 : "=r"(r0), "=r"(r1) : "r"(a));
}
__device__ __forceinline__ void mma_f16(float c[4], const uint32_t a[4], const uint32_t b[2]) {
    asm volatile(
        "mma.sync.aligned.m16n8k16.row.col.f32.f16.f16.f32 "
        "{%0,%1,%2,%3}, {%4,%5,%6,%7}, {%8,%9}, {%0,%1,%2,%3};"
        : "+f"(c[0]), "+f"(c[1]), "+f"(c[2]), "+f"(c[3])
        : "r"(a[0]), "r"(a[1]), "r"(a[2]), "r"(a[3]), "r"(b[0]), "r"(b[1]));
}

__device__ __forceinline__ void fill_tile(char* sm, const uint4* __restrict__ src, int tid) {
#pragma unroll
    for (int it = 0; it < 8; it++) {
        int c = it * 256 + tid;
        int row = c >> 4, ch = c & 15;
        *reinterpret_cast<uint4*>(sm + SWZ(row, ch)) = src[c];
    }
}

// 128x128 CTA tile, 8 warps (2x4), warp tile 64x32 (bias + kC path)
__device__ __forceinline__ void mma_tile(const char* smA, const char* smB,
                                         int lane, int wm, int wn, float acc[4][4][4]) {
#pragma unroll
    for (int mt = 0; mt < 4; mt++)
#pragma unroll
        for (int nt = 0; nt < 4; nt++)
#pragma unroll
            for (int q = 0; q < 4; q++) acc[mt][nt][q] = 0.0f;
    uint32_t sbA = smem_u32(smA), sbB = smem_u32(smB);
    const int mbase = wm * 64, nbase = wn * 32;
    const int arow = lane & 15, ach = lane >> 4;
    const int brow = lane & 7,  bch = (lane >> 3) & 1;
#pragma unroll
    for (int ks = 0; ks < 8; ks++) {
        const int k0c = ks * 2;
        uint32_t a[4][4], b[4][2];
#pragma unroll
        for (int mt = 0; mt < 4; mt++)
            ldmx4(a[mt][0], a[mt][1], a[mt][2], a[mt][3],
                  sbA + SWZ(mbase + mt * 16 + arow, k0c + ach));
#pragma unroll
        for (int nt = 0; nt < 4; nt++)
            ldmx2(b[nt][0], b[nt][1], sbB + SWZ(nbase + nt * 8 + brow, k0c + bch));
#pragma unroll
        for (int mt = 0; mt < 4; mt++)
#pragma unroll
            for (int nt = 0; nt < 4; nt++)
                mma_f16(acc[mt][nt], a[mt], b[nt]);
    }
}

template <int N>
__device__ __forceinline__ void red3(float* p) {
#pragma unroll
    for (int m = 4; m <= 16; m <<= 1)
#pragma unroll
        for (int i = 0; i < N; i++) p[i] += __shfl_xor_sync(FULLMASK, p[i], m);
}

// ======================= kD: unified delta GEMM (PDL-aware, R12 inner loop) =======
// Warp tile 64M x 32N (2 wm x 4 wn).
// mode 0: D0[j,s] over K=(i,k) 4096; 16 K-splits x 2 chunks; + 3 bias-block CTAs.
// mode 1: D1[j,s] over K=(e,k) 16384; 16 K-splits x 8 chunks.
__global__ __launch_bounds__(256, 2)
void kD(int mode)
{
    extern __shared__ char sm[];
    const int tid = threadIdx.x, w = tid >> 5, lane = tid & 31;
    const int s0 = blockIdx.y * 128;

    const __half* Abase; int arow; const float* H; float* dstP; int nch, nb;
    if (mode == 0) { Abase = g_Mh;                arow = 4096;  H = g_XT;  dstP = g_D0P; nch = 2; nb = 16; }
    else           { Abase = g_Mh + 33u * 16384u; arow = 16384; H = g_H1T; dstP = g_D1P; nch = 8; nb = 1 << 30; }

    if (mode == 0) { gdc_wait(); gdc_launch(); }

    if ((int)blockIdx.x >= nb) {
        // plain bias-block GEMM tile -> g_BD
        int bi = blockIdx.x - nb;
        int r = (bi == 0) ? 32 : (bi == 1) ? 161 : 178;
        char* smA = sm; char* smB = sm + 32768;
        fill_tile(smA, reinterpret_cast<const uint4*>(g_Mh + (size_t)r * 16384), tid);
        fill_tile(smB, reinterpret_cast<const uint4*>(g_Zh + (size_t)s0 * 128), tid);
        __syncthreads();
        float acc[4][4][4];
        mma_tile(smA, smB, lane, w & 1, w >> 1, acc);
        float* dst = g_BD + (size_t)bi * 128 * 2048;
        const int wm2 = w & 1, wn2 = w >> 1;
#pragma unroll
        for (int mt = 0; mt < 4; mt++)
#pragma unroll
            for (int qh = 0; qh < 2; qh++) {
                const int e = wm2 * 64 + mt * 16 + (lane >> 2) + 8 * qh;
#pragma unroll
                for (int nt = 0; nt < 4; nt++) {
                    const int s = wn2 * 32 + nt * 8 + 2 * (lane & 3);
                    *reinterpret_cast<float2*>(dst + (size_t)e * 2048 + s0 + s) =
                        make_float2(acc[mt][nt][2 * qh + 0], acc[mt][nt][2 * qh + 1]);
                }
            }
        return;
    }

    char*  zsm  = sm;                                      // 32K z tile (swizzled)
    float* hsm  = reinterpret_cast<float*>(sm + 32768);    // [nch e][128 s]
    char*  abuf = sm + 36864;                              // 2 x 32K A stages
    const int ksp = blockIdx.x;
    const int e0 = ksp * nch;
    const int wm = w & 1, wn = w >> 1;                     // 2 x 4 warp grid
    const int mbase = wm * 64, nbase = wn * 32;

    auto issueA = [&](int c) {
        char* buf = abuf + (c & 1) * 32768;
        const char* base = reinterpret_cast<const char*>(Abase) + (size_t)(e0 + c) * 256;
#pragma unroll
        for (int it = 0; it < 8; it++) {
            int idx = it * 256 + tid;
            int row = idx >> 4, ch = idx & 15;
            const char* src = base + (size_t)row * arow * 2 + ch * 16;
            uint32_t dst = smem_u32(buf + SWZ(row, ch));
            asm volatile("cp.async.cg.shared.global [%0], [%1], 16;" :: "r"(dst), "l"(src));
        }
        asm volatile("cp.async.commit_group;");
    };

    // Prologue (mode 1: reads only k1 outputs — ≥2 launches back — legal pre-wait)
    issueA(0);
    if (nch > 1) issueA(1);
#pragma unroll
    for (int it = 0; it < 8; it++) {
        int c = it * 256 + tid;
        int row = c >> 4, ch = c & 15;
        *reinterpret_cast<uint4*>(zsm + SWZ(row, ch)) =
            reinterpret_cast<const uint4*>(g_Zh + (size_t)s0 * 128)[c];
    }

    if (mode == 1) { gdc_wait(); gdc_launch(); }

    for (int c = tid; c < nch * 128; c += 256) {
        int ce = c >> 7, s = c & 127;
        hsm[ce * 128 + s] = H[(size_t)(e0 + ce) * 2048 + s0 + s];
    }

    float acc[4][4][4];
#pragma unroll
    for (int mt = 0; mt < 4; mt++)
#pragma unroll
        for (int nt = 0; nt < 4; nt++)
#pragma unroll
            for (int q = 0; q < 4; q++) acc[mt][nt][q] = 0.0f;

    const int arl = lane & 15, ach = lane >> 4;
    const int nidx = lane >> 2;
    const int bro = ((lane >> 4) << 3) + (lane & 7);   // 16-row x4 B load pattern
    const int bch = (lane >> 3) & 1;
    const uint32_t sbB = smem_u32(zsm);

#pragma unroll 1
    for (int c = 0; c < nch; c++) {
        if (c < nch - 1) asm volatile("cp.async.wait_group 1;");
        else             asm volatile("cp.async.wait_group 0;");
        __syncthreads();
        uint32_t sbA = smem_u32(abuf + (c & 1) * 32768);
        __half2 hs[4];
#pragma unroll
        for (int nt = 0; nt < 4; nt++)
            hs[nt] = __float2half2_rn(hsm[c * 128 + nbase + nt * 8 + nidx]);
#pragma unroll
        for (int ks = 0; ks < 8; ks++) {
            uint32_t b[4][2];
#pragma unroll
            for (int p = 0; p < 2; p++) {
                uint32_t z4[4];
                ldmx4(z4[0], z4[1], z4[2], z4[3],
                      sbB + SWZ(nbase + p * 16 + bro, ks * 2 + bch));
#pragma unroll
                for (int half = 0; half < 2; half++) {
                    const int nt = 2 * p + half;
                    __half2 b0h = __hmul2(*reinterpret_cast<__half2*>(&z4[2 * half + 0]), hs[nt]);
                    __half2 b1h = __hmul2(*reinterpret_cast<__half2*>(&z4[2 * half + 1]), hs[nt]);
                    b[nt][0] = *reinterpret_cast<uint32_t*>(&b0h);
                    b[nt][1] = *reinterpret_cast<uint32_t*>(&b1h);
                }
            }
#pragma unroll
            for (int mt = 0; mt < 4; mt++) {
                uint32_t a[4];
                ldmx4(a[0], a[1], a[2], a[3],
                      sbA + SWZ(mbase + mt * 16 + arl, ks * 2 + ach));
#pragma unroll
                for (int nt = 0; nt < 4; nt++)
                    mma_f16(acc[mt][nt], a, b[nt]);
            }
        }
        __syncthreads();
        if (c + 2 < nch) issueA(c + 2);
    }

    float* dst = dstP + (size_t)ksp * 128 * 2048;
#pragma unroll
    for (int mt = 0; mt < 4; mt++)
#pragma unroll
        for (int qh = 0; qh < 2; qh++) {
            const int j = mbase + mt * 16 + (lane >> 2) + 8 * qh;
#pragma unroll
            for (int nt = 0; nt < 4; nt++) {
                const int s = nbase + nt * 8 + 2 * (lane & 3);
                *reinterpret_cast<float2*>(dst + (size_t)j * 2048 + s0 + s) =
                    make_float2(acc[mt][nt][2 * qh + 0], acc[mt][nt][2 * qh + 1]);
            }
        }
}

// ======================= h1fin: h1 = relu(W0 x + b0 + bd0 + sum(D0P)) =============
__global__ __launch_bounds__(256)
void h1fin(const float* __restrict__ x, const float* __restrict__ W0, const float* __restrict__ b0)
{
    __shared__ float xsm[128 * 32];
    __shared__ float w0sm[16 * 32];
    const int tid = threadIdx.x;
    const int s0 = blockIdx.x * 128, jg = blockIdx.y;

    for (int c = tid; c < 4096; c += 256) {
        int s = c >> 5, i = c & 31;
        xsm[s * 32 + i] = x[(s0 + s) * 32 + i];
    }
    for (int c = tid; c < 512; c += 256) w0sm[c] = W0[jg * 512 + c];
    __syncthreads();

    gdc_wait(); gdc_launch();

    const int s = tid & 127, jh = tid >> 7;
#pragma unroll
    for (int jj = 0; jj < 8; jj++) {
        const int jl = jh * 8 + jj, j = jg * 16 + jl;
        float a = b0[j] + g_BD[(size_t)j * 2048 + s0 + s];
#pragma unroll
        for (int p = 0; p < 16; p++)
            a += g_D0P[((size_t)p * 128 + j) * 2048 + s0 + s];
#pragma unroll
        for (int i = 0; i < 32; i++) a = fmaf(w0sm[jl * 32 + i], xsm[s * 32 + i], a);
        g_H1T[(size_t)j * 2048 + s0 + s] = fmaxf(a, 0.0f);
    }
}

// ======================= h2fin: h2 = relu(W1 h1 + b1 + bd1 + sum(D1P)) ============
__global__ __launch_bounds__(256)
void h2fin(const float* __restrict__ W1, const float* __restrict__ b1)
{
    extern __shared__ float smf[];
    float* h1sm = smf;            // [128 e][128 s]
    float* w1sm = smf + 16384;    // [16][128]
    const int tid = threadIdx.x;
    const int s0 = blockIdx.x * 128, jg = blockIdx.y;

    for (int c = tid; c < 4096; c += 256) {
        int e = c >> 5, ch = c & 31;
        reinterpret_cast<float4*>(h1sm)[c] =
            *reinterpret_cast<const float4*>(g_H1T + (size_t)e * 2048 + s0 + ch * 4);
    }
    for (int c = tid; c < 2048; c += 256) w1sm[c] = W1[jg * 2048 + c];
    __syncthreads();

    gdc_wait(); gdc_launch();

    const int s = tid & 127, jh = tid >> 7;
    float a[8];
#pragma unroll
    for (int jj = 0; jj < 8; jj++) {
        const int j = jg * 16 + jh * 8 + jj;
        float acc = b1[j] + g_BD[(size_t)(128 + j) * 2048 + s0 + s];
#pragma unroll
        for (int p = 0; p < 16; p++)
            acc += g_D1P[((size_t)p * 128 + j) * 2048 + s0 + s];
        a[jj] = acc;
    }
#pragma unroll 4
    for (int e = 0; e < 128; e++) {
        const float h = h1sm[e * 128 + s];
#pragma unroll
        for (int jj = 0; jj < 8; jj++)
            a[jj] = fmaf(w1sm[(jh * 8 + jj) * 128 + e], h, a[jj]);
    }
#pragma unroll
    for (int jj = 0; jj < 8; jj++) {
        const int j = jg * 16 + jh * 8 + jj;
        float v = fmaxf(a[jj], 0.0f);
        g_H2T[(size_t)j * 2048 + s0 + s] = v;
        g_H2h[(size_t)j * 2048 + s0 + s] = __float2half(v);
    }
}

// ======================= KC: layer-2 blocks (162..177) + output ===================
// h2 tile fp16 (32K) -> smem ~97K -> 2 CTAs/SM, single co-resident wave.
__global__ __launch_bounds__(256, 2)
void kC(const float* __restrict__ W2, const float* __restrict__ b2, float* __restrict__ out)
{
    extern __shared__ char sm[];
    char* smA = sm;
    char* smB = sm + 32768;
    __half* h2sm = reinterpret_cast<__half*>(sm + 65536);         // [128 e][128 s] fp16 (32K)
    float* w2sm = reinterpret_cast<float*>(sm + 65536 + 32768);   // [128]
    float* sd = w2sm + 128;                                       // [2][128]
    const int tid = threadIdx.x, w = tid >> 5, lane = tid & 31;
    const int wm = w & 1, wn = w >> 1;
    const int jj = blockIdx.x;
    const int s0 = blockIdx.y * 128;

    // prologue: A/z tiles (k1 data) + W2 — overlaps h2fin
    fill_tile(smA, reinterpret_cast<const uint4*>(g_Mh + (size_t)(162 + jj) * 16384), tid);
    fill_tile(smB, reinterpret_cast<const uint4*>(g_Zh + (size_t)s0 * 128), tid);
    if (tid < 128) w2sm[tid] = W2[jj * 128 + tid];

    gdc_wait(); gdc_launch();

    // h2 fp16 tile: 128 rows x 256B = 2048 uint4 chunks
    for (int c = tid; c < 2048; c += 256) {
        int e = c >> 4, ch = c & 15;
        reinterpret_cast<uint4*>(h2sm)[e * 16 + ch] =
            *reinterpret_cast<const uint4*>(g_H2h + (size_t)e * 2048 + s0 + ch * 8);
    }
    __syncthreads();

    float acc[4][4][4];
    mma_tile(smA, smB, lane, wm, wn, acc);

    float pb[8];
#pragma unroll
    for (int i = 0; i < 8; i++) pb[i] = 0.0f;
#pragma unroll
    for (int mt = 0; mt < 4; mt++)
#pragma unroll
        for (int qh = 0; qh < 2; qh++) {
            const int e = wm * 64 + mt * 16 + (lane >> 2) + 8 * qh;
            const float wv = w2sm[e];
            const __half2* hrow = reinterpret_cast<const __half2*>(h2sm + e * 128);
#pragma unroll
            for (int nt = 0; nt < 4; nt++) {
                const int sb = wn * 32 + nt * 8 + 2 * (lane & 3);
                float2 hv = __half22float2(hrow[sb >> 1]);
                pb[nt * 2 + 0] += (acc[mt][nt][2 * qh + 0] + wv) * hv.x;
                pb[nt * 2 + 1] += (acc[mt][nt][2 * qh + 1] + wv) * hv.y;
            }
        }
    red3<8>(pb);
    if (lane < 4) {
#pragma unroll
        for (int nt = 0; nt < 4; nt++)
#pragma unroll
            for (int q01 = 0; q01 < 2; q01++)
                sd[wm * 128 + wn * 32 + nt * 8 + 2 * lane + q01] = pb[nt * 2 + q01];
    }
    __syncthreads();
    if (tid < 128)
        out[(size_t)(s0 + tid) * 16 + jj] =
            b2[jj] + g_BD[(size_t)(256 + jj) * 2048 + s0 + tid] + sd[tid] + sd[128 + tid];
}

// ======================= launch ===================================================
template <typename F, typename... Args>
static inline void launch_pdl(F kern, dim3 grid, dim3 block, size_t smem, Args... args) {
    cudaLaunchConfig_t cfg = {};
    cfg.gridDim = grid;
    cfg.blockDim = block;
    cfg.dynamicSmemBytes = smem;
    cfg.stream = 0;
    cudaLaunchAttribute attrs[1];
    attrs[0].id = cudaLaunchAttributeProgrammaticStreamSerialization;
    attrs[0].val.programmaticStreamSerializationAllowed = 1;
    cfg.attrs = attrs;
    cfg.numAttrs = 1;
    cudaLaunchKernelEx(&cfg, kern, args...);
}

extern "C" void kernel_launch(void* const* d_in, const int* in_sizes, int n_in,
                              void* d_out, int out_size) {
    (void)in_sizes; (void)n_in; (void)out_size;
    const float* x   = (const float*)d_in[0];
    const float* z   = (const float*)d_in[1];
    const float* W0  = (const float*)d_in[2];
    const float* b0  = (const float*)d_in[3];
    const float* W1  = (const float*)d_in[4];
    const float* b1  = (const float*)d_in[5];
    const float* W2  = (const float*)d_in[6];
    const float* b2  = (const float*)d_in[7];
    const float* ffB = (const float*)d_in[8];
    const float* ffG = (const float*)d_in[9];
    const float* ffS = (const float*)d_in[10];
    const int*   ffP = (const int*)d_in[11];
    float* out = (float*)d_out;

    cudaFuncSetAttribute(kD, cudaFuncAttributeMaxDynamicSharedMemorySize, 102400);
    cudaFuncSetAttribute(h2fin, cudaFuncAttributeMaxDynamicSharedMemorySize, 73728);
    cudaFuncSetAttribute(kC, cudaFuncAttributeMaxDynamicSharedMemorySize, 100352);

    k1_build<<<430, 256>>>(x, z, ffB, ffG, ffS, ffP);
    launch_pdl(kD, dim3(19, 16), dim3(256), (size_t)102400, 0);     // D0 partials + bias blocks
    launch_pdl(h1fin, dim3(16, 8), dim3(256), (size_t)0, x, W0, b0);
    launch_pdl(kD, dim3(16, 16), dim3(256), (size_t)102400, 1);     // D1 partials
    launch_pdl(h2fin, dim3(16, 8), dim3(256), (size_t)73728, W1, b1);
    launch_pdl(kC, dim3(16, 16), dim3(256), (size_t)100352, W2, b2, out);
}

// round 15
// speedup vs baseline: 1.0246x; 1.0083x over previous
#include <cuda_runtime.h>
#include <cuda_fp16.h>
#include <cstdint>

#define FULLMASK 0xFFFFFFFFu

// ======================= device scratch (no allocs allowed) =======================
__device__ __align__(16) __half g_Mh[179u * 128u * 128u];   // per-block linear maps, fp16
__device__ __align__(16) __half g_Zh[2048u * 128u];         // z in fp16
__device__ __align__(16) float  g_XT[32u * 2048u];          // x transposed [i][s]
__device__ __align__(16) float  g_H1T[128u * 2048u];        // h1 fp32 [j][s]
__device__ __align__(16) float  g_H2T[128u * 2048u];        // h2 fp32 [j][s]
__device__ __align__(16) __half g_H2h[128u * 2048u];        // h2 fp16 [j][s] (for kC)
__device__ __align__(16) float  g_D0P[16u * 128u * 2048u];  // layer-0 delta partials
__device__ __align__(16) float  g_D1P[16u * 128u * 2048u];  // layer-1 delta partials
__device__ __align__(16) float  g_BD[3u * 128u * 2048u];    // bias deltas (blocks 32,161,178)

__device__ __forceinline__ uint32_t smem_u32(const void* p) {
    uint32_t a;
    asm("{ .reg .u64 t; cvta.to.shared.u64 t, %1; cvt.u32.u64 %0, t; }" : "=r"(a) : "l"(p));
    return a;
}
// PDL controls (sm_90+)
__device__ __forceinline__ void gdc_wait() {
#if __CUDA_ARCH__ >= 900
    asm volatile("griddepcontrol.wait;" ::: "memory");
#endif
}
__device__ __forceinline__ void gdc_launch() {
#if __CUDA_ARCH__ >= 900
    asm volatile("griddepcontrol.launch_dependents;");
#endif
}

// ======================= FWHT (contiguous layout) =======================
__device__ __forceinline__ void fwht128c(float &u0, float &u1, float &u2, float &u3, int lane) {
    float a0 = u0 + u1, a1 = u0 - u1;
    float a2 = u2 + u3, a3 = u2 - u3;
    u0 = a0 + a2; u2 = a0 - a2;
    u1 = a1 + a3; u3 = a1 - a3;
#pragma unroll
    for (int m = 1; m <= 16; m <<= 1) {
        float s = (lane & m) ? -1.0f : 1.0f;
        float p0 = __shfl_xor_sync(FULLMASK, u0, m);
        float p1 = __shfl_xor_sync(FULLMASK, u1, m);
        float p2 = __shfl_xor_sync(FULLMASK, u2, m);
        float p3 = __shfl_xor_sync(FULLMASK, u3, m);
        u0 = fmaf(s, u0, p0); u1 = fmaf(s, u1, p1);
        u2 = fmaf(s, u2, p2); u3 = fmaf(s, u3, p3);
    }
}

// ======================= K1: build M rows + z->fp16 + x transpose ================
// One warp builds 8 rows of ONE block r, loading ffB/ffG/ffP once (L2 traffic /8).
__global__ __launch_bounds__(256)
void k1_build(const float* __restrict__ x, const float* __restrict__ z,
              const float* __restrict__ ffB, const float* __restrict__ ffG,
              const float* __restrict__ ffS, const int* __restrict__ ffP)
{
    __shared__ __align__(16) float sstg[8][2][128];
    const int tid = threadIdx.x, w = tid >> 5, lane = tid & 31;

    if (blockIdx.x >= 422) {
        __shared__ float xs[256][33];
        int s0 = (blockIdx.x - 422) * 256;
        const float4* xr = reinterpret_cast<const float4*>(x + (size_t)(s0 + tid) * 32);
#pragma unroll
        for (int i4 = 0; i4 < 8; i4++) {
            float4 v = xr[i4];
            xs[tid][i4 * 4 + 0] = v.x; xs[tid][i4 * 4 + 1] = v.y;
            xs[tid][i4 * 4 + 2] = v.z; xs[tid][i4 * 4 + 3] = v.w;
        }
        __syncthreads();
#pragma unroll
        for (int it = 0; it < 32; it++) {
            int idx = it * 256 + tid;
            int i = idx >> 8, sl = idx & 255;
            g_XT[(size_t)i * 2048 + s0 + sl] = xs[sl][i];
        }
        return;
    }
    if (blockIdx.x >= 358) {
        int gt = (blockIdx.x - 358) * 256 + tid;
        const float4* zf4 = reinterpret_cast<const float4*>(z);
        uint2* zb2 = reinterpret_cast<uint2*>(g_Zh);
#pragma unroll
        for (int it = 0; it < 4; it++) {
            int i = gt * 4 + it;
            float4 v = zf4[i];
            __half2 lo = __floats2half2_rn(v.x, v.y);
            __half2 hi = __floats2half2_rn(v.z, v.w);
            uint2 o;
            o.x = *reinterpret_cast<uint32_t*>(&lo);
            o.y = *reinterpret_cast<uint32_t*>(&hi);
            zb2[i] = o;
        }
        return;
    }

    const int wg = blockIdx.x * 8 + w;        // 0..2863
    const int r  = wg >> 4;                   // block 0..178
    const int mb = (wg & 15) * 8;
    const int o  = r * 128;

    float4 g4 = reinterpret_cast<const float4*>(ffG + o)[lane];
    float4 b4 = reinterpret_cast<const float4*>(ffB + o)[lane];
    int4   p4 = reinterpret_cast<const int4*>(ffP + o)[lane];

    const int e = lane << 2;
#pragma unroll 1
    for (int q = 0; q < 8; q++) {
        const int m = mb + q;
        const float smv = ffS[o + m] * (1.0f / 128.0f);

        float t0 = (__popc((e + 0) & m) & 1) ? -g4.x : g4.x;
        float t1 = (__popc((e + 1) & m) & 1) ? -g4.y : g4.y;
        float t2 = (__popc((e + 2) & m) & 1) ? -g4.z : g4.z;
        float t3 = (__popc((e + 3) & m) & 1) ? -g4.w : g4.w;

        float* stg = sstg[w][q & 1];
        stg[p4.x] = t0; stg[p4.y] = t1; stg[p4.z] = t2; stg[p4.w] = t3;
        __syncwarp();
        float4 u = *reinterpret_cast<float4*>(stg + e);
        fwht128c(u.x, u.y, u.z, u.w, lane);

        __half2 lo = __floats2half2_rn(smv * b4.x * u.x, smv * b4.y * u.y);
        __half2 hi = __floats2half2_rn(smv * b4.z * u.z, smv * b4.w * u.w);
        uint2 ov;
        ov.x = *reinterpret_cast<uint32_t*>(&lo);
        ov.y = *reinterpret_cast<uint32_t*>(&hi);
        reinterpret_cast<uint2*>(g_Mh + ((size_t)r * 128 + m) * 128)[lane] = ov;
    }
}

// ======================= shared MMA machinery =====================================
#define SWZ(row, ch) ((uint32_t)((row) * 256 + (((ch) ^ ((row) & 7)) << 4)))

__device__ __forceinline__ void ldmx4(uint32_t &r0, uint32_t &r1, uint32_t &r2, uint32_t &r3, uint32_t a) {
    asm volatile("ldmatrix.sync.aligned.m8n8.x4.shared.b16 {%0,%1,%2,%3}, [%4];"
                 : "=r"(r0), "=r"(r1), "=r"(r2), "=r"(r3) : "r"(a));
}
__device__ __forceinline__ void ldmx2(uint32_t &r0, uint32_t &r1, uint32_t a) {
    asm volatile("ldmatrix.sync.aligned.m8n8.x2.shared.b16 {%0,%1}, [%2];"
                 : "=r"(r0), "=r"(r1) : "r"(a));
}
__device__ __forceinline__ void mma_f16(float c[4], const uint32_t a[4], const uint32_t b[2]) {
    asm volatile(
        "mma.sync.aligned.m16n8k16.row.col.f32.f16.f16.f32 "
        "{%0,%1,%2,%3}, {%4,%5,%6,%7}, {%8,%9}, {%0,%1,%2,%3};"
        : "+f"(c[0]), "+f"(c[1]), "+f"(c[2]), "+f"(c[3])
        : "r"(a[0]), "r"(a[1]), "r"(a[2]), "r"(a[3]), "r"(b[0]), "r"(b[1]));
}

__device__ __forceinline__ void fill_tile(char* sm, const uint4* __restrict__ src, int tid) {
#pragma unroll
    for (int it = 0; it < 8; it++) {
        int c = it * 256 + tid;
        int row = c >> 4, ch = c & 15;
        *reinterpret_cast<uint4*>(sm + SWZ(row, ch)) = src[c];
    }
}

// 128x128 CTA tile, 8 warps (2x4), warp tile 64x32 (bias + kC path)
__device__ __forceinline__ void mma_tile(const char* smA, const char* smB,
                                         int lane, int wm, int wn, float acc[4][4][4]) {
#pragma unroll
    for (int mt = 0; mt < 4; mt++)
#pragma unroll
        for (int nt = 0; nt < 4; nt++)
#pragma unroll
            for (int q = 0; q < 4; q++) acc[mt][nt][q] = 0.0f;
    uint32_t sbA = smem_u32(smA), sbB = smem_u32(smB);
    const int mbase = wm * 64, nbase = wn * 32;
    const int arow = lane & 15, ach = lane >> 4;
    const int brow = lane & 7,  bch = (lane >> 3) & 1;
#pragma unroll
    for (int ks = 0; ks < 8; ks++) {
        const int k0c = ks * 2;
        uint32_t a[4][4], b[4][2];
#pragma unroll
        for (int mt = 0; mt < 4; mt++)
            ldmx4(a[mt][0], a[mt][1], a[mt][2], a[mt][3],
                  sbA + SWZ(mbase + mt * 16 + arow, k0c + ach));
#pragma unroll
        for (int nt = 0; nt < 4; nt++)
            ldmx2(b[nt][0], b[nt][1], sbB + SWZ(nbase + nt * 8 + brow, k0c + bch));
#pragma unroll
        for (int mt = 0; mt < 4; mt++)
#pragma unroll
            for (int nt = 0; nt < 4; nt++)
                mma_f16(acc[mt][nt], a[mt], b[nt]);
    }
}

template <int N>
__device__ __forceinline__ void red3(float* p) {
#pragma unroll
    for (int m = 4; m <= 16; m <<= 1)
#pragma unroll
        for (int i = 0; i < N; i++) p[i] += __shfl_xor_sync(FULLMASK, p[i], m);
}

// ======================= kD: unified delta GEMM (PDL-aware) =======================
// Warp tile 64M x 32N (2 wm x 4 wn). Single-sync distance-1 pipeline:
//   loop: wait_group 0; __syncthreads; issueA(c+1); compute(c)
// mode 0: D0[j,s] over K=(i,k) 4096; 16 K-splits x 2 chunks; + bias block 32.
// mode 1: D1[j,s] over K=(e,k) 16384; 16 K-splits x 8 chunks; + bias blocks 161,178.
__global__ __launch_bounds__(256, 2)
void kD(int mode)
{
    extern __shared__ char sm[];
    const int tid = threadIdx.x, w = tid >> 5, lane = tid & 31;
    const int s0 = blockIdx.y * 128;

    const __half* Abase; int arow; const float* H; float* dstP; int nch;
    if (mode == 0) { Abase = g_Mh;                arow = 4096;  H = g_XT;  dstP = g_D0P; nch = 2; }
    else           { Abase = g_Mh + 33u * 16384u; arow = 16384; H = g_H1T; dstP = g_D1P; nch = 8; }

    if (mode == 0) { gdc_wait(); gdc_launch(); }

    if ((int)blockIdx.x >= 16) {
        // bias-block GEMM tile -> g_BD. mode0: bi=0 (block 32); mode1: bi=1,2 (161,178).
        int bi = (int)blockIdx.x - 16 + (mode == 0 ? 0 : 1);
        if (mode == 1) gdc_launch();   // reads only k1 data; no wait needed
        int r = (bi == 0) ? 32 : (bi == 1) ? 161 : 178;
        char* smA = sm; char* smB = sm + 32768;
        fill_tile(smA, reinterpret_cast<const uint4*>(g_Mh + (size_t)r * 16384), tid);
        fill_tile(smB, reinterpret_cast<const uint4*>(g_Zh + (size_t)s0 * 128), tid);
        __syncthreads();
        float acc[4][4][4];
        mma_tile(smA, smB, lane, w & 1, w >> 1, acc);
        float* dst = g_BD + (size_t)bi * 128 * 2048;
        const int wm2 = w & 1, wn2 = w >> 1;
#pragma unroll
        for (int mt = 0; mt < 4; mt++)
#pragma unroll
            for (int qh = 0; qh < 2; qh++) {
                const int e = wm2 * 64 + mt * 16 + (lane >> 2) + 8 * qh;
#pragma unroll
                for (int nt = 0; nt < 4; nt++) {
                    const int s = wn2 * 32 + nt * 8 + 2 * (lane & 3);
                    *reinterpret_cast<float2*>(dst + (size_t)e * 2048 + s0 + s) =
                        make_float2(acc[mt][nt][2 * qh + 0], acc[mt][nt][2 * qh + 1]);
                }
            }
        return;
    }

    char*  zsm  = sm;                                      // 32K z tile (swizzled)
    float* hsm  = reinterpret_cast<float*>(sm + 32768);    // [nch e][128 s]
    char*  abuf = sm + 36864;                              // 2 x 32K A stages
    const int ksp = blockIdx.x;
    const int e0 = ksp * nch;
    const int wm = w & 1, wn = w >> 1;                     // 2 x 4 warp grid
    const int mbase = wm * 64, nbase = wn * 32;

    auto issueA = [&](int c) {
        char* buf = abuf + (c & 1) * 32768;
        const char* base = reinterpret_cast<const char*>(Abase) + (size_t)(e0 + c) * 256;
#pragma unroll
        for (int it = 0; it < 8; it++) {
            int idx = it * 256 + tid;
            int row = idx >> 4, ch = idx & 15;
            const char* src = base + (size_t)row * arow * 2 + ch * 16;
            uint32_t dst = smem_u32(buf + SWZ(row, ch));
            asm volatile("cp.async.cg.shared.global [%0], [%1], 16;" :: "r"(dst), "l"(src));
        }
        asm volatile("cp.async.commit_group;");
    };

    // Prologue (mode 1: reads only k1 outputs pre-wait — legal)
    issueA(0);
#pragma unroll
    for (int it = 0; it < 8; it++) {
        int c = it * 256 + tid;
        int row = c >> 4, ch = c & 15;
        *reinterpret_cast<uint4*>(zsm + SWZ(row, ch)) =
            reinterpret_cast<const uint4*>(g_Zh + (size_t)s0 * 128)[c];
    }

    if (mode == 1) { gdc_wait(); gdc_launch(); }

    for (int c = tid; c < nch * 128; c += 256) {
        int ce = c >> 7, s = c & 127;
        hsm[ce * 128 + s] = H[(size_t)(e0 + ce) * 2048 + s0 + s];
    }
    // NOTE: no prologue sync — iteration 0's barrier covers zsm/hsm visibility.

    float acc[4][4][4];
#pragma unroll
    for (int mt = 0; mt < 4; mt++)
#pragma unroll
        for (int nt = 0; nt < 4; nt++)
#pragma unroll
            for (int q = 0; q < 4; q++) acc[mt][nt][q] = 0.0f;

    const int arl = lane & 15, ach = lane >> 4;
    const int nidx = lane >> 2;
    const int bro = ((lane >> 4) << 3) + (lane & 7);   // 16-row x4 B load pattern
    const int bch = (lane >> 3) & 1;
    const uint32_t sbB = smem_u32(zsm);

#pragma unroll 1
    for (int c = 0; c < nch; c++) {
        asm volatile("cp.async.wait_group 0;");
        __syncthreads();                 // chunk c visible; buf (c+1)&1 free
        if (c + 1 < nch) issueA(c + 1);  // loads overlap compute(c)
        uint32_t sbA = smem_u32(abuf + (c & 1) * 32768);
        __half2 hs[4];
#pragma unroll
        for (int nt = 0; nt < 4; nt++)
            hs[nt] = __float2half2_rn(hsm[c * 128 + nbase + nt * 8 + nidx]);
#pragma unroll
        for (int ks = 0; ks < 8; ks++) {
            uint32_t b[4][2];
#pragma unroll
            for (int p = 0; p < 2; p++) {
                uint32_t z4[4];
                ldmx4(z4[0], z4[1], z4[2], z4[3],
                      sbB + SWZ(nbase + p * 16 + bro, ks * 2 + bch));
#pragma unroll
                for (int half = 0; half < 2; half++) {
                    const int nt = 2 * p + half;
                    __half2 b0h = __hmul2(*reinterpret_cast<__half2*>(&z4[2 * half + 0]), hs[nt]);
                    __half2 b1h = __hmul2(*reinterpret_cast<__half2*>(&z4[2 * half + 1]), hs[nt]);
                    b[nt][0] = *reinterpret_cast<uint32_t*>(&b0h);
                    b[nt][1] = *reinterpret_cast<uint32_t*>(&b1h);
                }
            }
#pragma unroll
            for (int mt = 0; mt < 4; mt++) {
                uint32_t a[4];
                ldmx4(a[0], a[1], a[2], a[3],
                      sbA + SWZ(mbase + mt * 16 + arl, ks * 2 + ach));
#pragma unroll
                for (int nt = 0; nt < 4; nt++)
                    mma_f16(acc[mt][nt], a, b[nt]);
            }
        }
    }

    float* dst = dstP + (size_t)ksp * 128 * 2048;
#pragma unroll
    for (int mt = 0; mt < 4; mt++)
#pragma unroll
        for (int qh = 0; qh < 2; qh++) {
            const int j = mbase + mt * 16 + (lane >> 2) + 8 * qh;
#pragma unroll
            for (int nt = 0; nt < 4; nt++) {
                const int s = nbase + nt * 8 + 2 * (lane & 3);
                *reinterpret_cast<float2*>(dst + (size_t)j * 2048 + s0 + s) =
                    make_float2(acc[mt][nt][2 * qh + 0], acc[mt][nt][2 * qh + 1]);
            }
        }
}

// ======================= h1fin: h1 = relu(W0 x + b0 + bd0 + sum(D0P)) =============
__global__ __launch_bounds__(256)
void h1fin(const float* __restrict__ x, const float* __restrict__ W0, const float* __restrict__ b0)
{
    __shared__ float xsm[128 * 32];
    __shared__ float w0sm[16 * 32];
    const int tid = threadIdx.x;
    const int s0 = blockIdx.x * 128, jg = blockIdx.y;

    for (int c = tid; c < 4096; c += 256) {
        int s = c >> 5, i = c & 31;
        xsm[s * 32 + i] = x[(s0 + s) * 32 + i];
    }
    for (int c = tid; c < 512; c += 256) w0sm[c] = W0[jg * 512 + c];
    __syncthreads();

    gdc_wait(); gdc_launch();

    const int s = tid & 127, jh = tid >> 7;
#pragma unroll
    for (int jj = 0; jj < 8; jj++) {
        const int jl = jh * 8 + jj, j = jg * 16 + jl;
        float a = b0[j] + g_BD[(size_t)j * 2048 + s0 + s];
#pragma unroll
        for (int p = 0; p < 16; p++)
            a += g_D0P[((size_t)p * 128 + j) * 2048 + s0 + s];
#pragma unroll
        for (int i = 0; i < 32; i++) a = fmaf(w0sm[jl * 32 + i], xsm[s * 32 + i], a);
        g_H1T[(size_t)j * 2048 + s0 + s] = fmaxf(a, 0.0f);
    }
}

// ======================= h2fin: h2 = relu(W1 h1 + b1 + bd1 + sum(D1P)) ============
__global__ __launch_bounds__(256)
void h2fin(const float* __restrict__ W1, const float* __restrict__ b1)
{
    extern __shared__ float smf[];
    float* h1sm = smf;            // [128 e][128 s]
    float* w1sm = smf + 16384;    // [16][128]
    const int tid = threadIdx.x;
    const int s0 = blockIdx.x * 128, jg = blockIdx.y;

    for (int c = tid; c < 4096; c += 256) {
        int e = c >> 5, ch = c & 31;
        reinterpret_cast<float4*>(h1sm)[c] =
            *reinterpret_cast<const float4*>(g_H1T + (size_t)e * 2048 + s0 + ch * 4);
    }
    for (int c = tid; c < 2048; c += 256) w1sm[c] = W1[jg * 2048 + c];
    __syncthreads();

    gdc_wait(); gdc_launch();

    const int s = tid & 127, jh = tid >> 7;
    float a[8];
#pragma unroll
    for (int jj = 0; jj < 8; jj++) {
        const int j = jg * 16 + jh * 8 + jj;
        float acc = b1[j] + g_BD[(size_t)(128 + j) * 2048 + s0 + s];
#pragma unroll
        for (int p = 0; p < 16; p++)
            acc += g_D1P[((size_t)p * 128 + j) * 2048 + s0 + s];
        a[jj] = acc;
    }
#pragma unroll 4
    for (int e = 0; e < 128; e++) {
        const float h = h1sm[e * 128 + s];
#pragma unroll
        for (int jj = 0; jj < 8; jj++)
            a[jj] = fmaf(w1sm[(jh * 8 + jj) * 128 + e], h, a[jj]);
    }
#pragma unroll
    for (int jj = 0; jj < 8; jj++) {
        const int j = jg * 16 + jh * 8 + jj;
        float v = fmaxf(a[jj], 0.0f);
        g_H2T[(size_t)j * 2048 + s0 + s] = v;
        g_H2h[(size_t)j * 2048 + s0 + s] = __float2half(v);
    }
}

// ======================= KC: layer-2 blocks (162..177) + output ===================
// h2 tile fp16 (32K) -> smem ~97K -> 2 CTAs/SM, single co-resident wave.
__global__ __launch_bounds__(256, 2)
void kC(const float* __restrict__ W2, const float* __restrict__ b2, float* __restrict__ out)
{
    extern __shared__ char sm[];
    char* smA = sm;
    char* smB = sm + 32768;
    __half* h2sm = reinterpret_cast<__half*>(sm + 65536);         // [128 e][128 s] fp16 (32K)
    float* w2sm = reinterpret_cast<float*>(sm + 65536 + 32768);   // [128]
    float* sd = w2sm + 128;                                       // [2][128]
    const int tid = threadIdx.x, w = tid >> 5, lane = tid & 31;
    const int wm = w & 1, wn = w >> 1;
    const int jj = blockIdx.x;
    const int s0 = blockIdx.y * 128;

    // prologue: A/z tiles (k1 data) + W2 — overlaps h2fin
    fill_tile(smA, reinterpret_cast<const uint4*>(g_Mh + (size_t)(162 + jj) * 16384), tid);
    fill_tile(smB, reinterpret_cast<const uint4*>(g_Zh + (size_t)s0 * 128), tid);
    if (tid < 128) w2sm[tid] = W2[jj * 128 + tid];

    gdc_wait(); gdc_launch();

    for (int c = tid; c < 2048; c += 256) {
        int e = c >> 4, ch = c & 15;
        reinterpret_cast<uint4*>(h2sm)[e * 16 + ch] =
            *reinterpret_cast<const uint4*>(g_H2h + (size_t)e * 2048 + s0 + ch * 8);
    }
    __syncthreads();

    float acc[4][4][4];
    mma_tile(smA, smB, lane, wm, wn, acc);

    float pb[8];
#pragma unroll
    for (int i = 0; i < 8; i++) pb[i] = 0.0f;
#pragma unroll
    for (int mt = 0; mt < 4; mt++)
#pragma unroll
        for (int qh = 0; qh < 2; qh++) {
            const int e = wm * 64 + mt * 16 + (lane >> 2) + 8 * qh;
            const float wv = w2sm[e];
            const __half2* hrow = reinterpret_cast<const __half2*>(h2sm + e * 128);
#pragma unroll
            for (int nt = 0; nt < 4; nt++) {
                const int sb = wn * 32 + nt * 8 + 2 * (lane & 3);
                float2 hv = __half22float2(hrow[sb >> 1]);
                pb[nt * 2 + 0] += (acc[mt][nt][2 * qh + 0] + wv) * hv.x;
                pb[nt * 2 + 1] += (acc[mt][nt][2 * qh + 1] + wv) * hv.y;
            }
        }
    red3<8>(pb);
    if (lane < 4) {
#pragma unroll
        for (int nt = 0; nt < 4; nt++)
#pragma unroll
            for (int q01 = 0; q01 < 2; q01++)
                sd[wm * 128 + wn * 32 + nt * 8 + 2 * lane + q01] = pb[nt * 2 + q01];
    }
    __syncthreads();
    if (tid < 128)
        out[(size_t)(s0 + tid) * 16 + jj] =
            b2[jj] + g_BD[(size_t)(256 + jj) * 2048 + s0 + tid] + sd[tid] + sd[128 + tid];
}

// ======================= launch ===================================================
template <typename F, typename... Args>
static inline void launch_pdl(F kern, dim3 grid, dim3 block, size_t smem, Args... args) {
    cudaLaunchConfig_t cfg = {};
    cfg.gridDim = grid;
    cfg.blockDim = block;
    cfg.dynamicSmemBytes = smem;
    cfg.stream = 0;
    cudaLaunchAttribute attrs[1];
    attrs[0].id = cudaLaunchAttributeProgrammaticStreamSerialization;
    attrs[0].val.programmaticStreamSerializationAllowed = 1;
    cfg.attrs = attrs;
    cfg.numAttrs = 1;
    cudaLaunchKernelEx(&cfg, kern, args...);
}

extern "C" void kernel_launch(void* const* d_in, const int* in_sizes, int n_in,
                              void* d_out, int out_size) {
    (void)in_sizes; (void)n_in; (void)out_size;
    const float* x   = (const float*)d_in[0];
    const float* z   = (const float*)d_in[1];
    const float* W0  = (const float*)d_in[2];
    const float* b0  = (const float*)d_in[3];
    const float* W1  = (const float*)d_in[4];
    const float* b1  = (const float*)d_in[5];
    const float* W2  = (const float*)d_in[6];
    const float* b2  = (const float*)d_in[7];
    const float* ffB = (const float*)d_in[8];
    const float* ffG = (const float*)d_in[9];
    const float* ffS = (const float*)d_in[10];
    const int*   ffP = (const int*)d_in[11];
    float* out = (float*)d_out;

    cudaFuncSetAttribute(kD, cudaFuncAttributeMaxDynamicSharedMemorySize, 102400);
    cudaFuncSetAttribute(h2fin, cudaFuncAttributeMaxDynamicSharedMemorySize, 73728);
    cudaFuncSetAttribute(kC, cudaFuncAttributeMaxDynamicSharedMemorySize, 100352);

    k1_build<<<430, 256>>>(x, z, ffB, ffG, ffS, ffP);
    launch_pdl(kD, dim3(17, 16), dim3(256), (size_t)102400, 0);     // D0 partials + bias 32
    launch_pdl(h1fin, dim3(16, 8), dim3(256), (size_t)0, x, W0, b0);
    launch_pdl(kD, dim3(18, 16), dim3(256), (size_t)102400, 1);     // D1 partials + bias 161,178
    launch_pdl(h2fin, dim3(16, 8), dim3(256), (size_t)73728, W1, b1);
    launch_pdl(kC, dim3(16, 16), dim3(256), (size_t)100352, W2, b2, out);
}